// round 3
// baseline (speedup 1.0000x reference)
#include <cuda_runtime.h>
#include <math.h>

#define LSEQ 2048
#define DMODEL 2048
#define QKVDIM 3072
#define HQ 16
#define HKV 4
#define HD 128

// ---------------- device scratch (no allocation allowed) ----------------
__device__ __align__(16) float g_proj[(size_t)LSEQ * QKVDIM];          //  25.2 MB
__device__ __align__(16) float g_Q[(size_t)HQ * LSEQ * HD];            //  16.8 MB
__device__ __align__(16) float g_K[(size_t)HKV * LSEQ * HD];           //   4.2 MB
__device__ __align__(16) float g_V[(size_t)HKV * LSEQ * HD];           //   4.2 MB
__device__ __align__(16) float g_S[(size_t)HQ * LSEQ * LSEQ];          // 268.4 MB
__device__ __align__(16) float g_AO[(size_t)LSEQ * DMODEL];            //  16.8 MB

// ---------------- generic fp32 GEMM: 128x128 block, 8x8/thread, BK=8 ----------------
// C[M,N] = A[M,K] @ B   (TRANS_B=0: B is [K,N] row-major; TRANS_B=1: B is [N,K] row-major)
// batch via blockIdx.z: A += z*aStr, B += (z/bDiv)*bStr, C += z*cStr
template <int TRANS_B>
__global__ __launch_bounds__(256, 2)
void gemm_kernel(const float* __restrict__ A, const float* __restrict__ B,
                 float* __restrict__ C,
                 int M, int N, int K, int lda, int ldb, int ldc,
                 long aStr, long bStr, int bDiv, long cStr)
{
    const int z = blockIdx.z;
    A += (long)z * aStr;
    B += (long)(z / bDiv) * bStr;
    C += (long)z * cStr;

    __shared__ float As[8][128];
    __shared__ float Bs[8][128];

    const int tid = threadIdx.x;
    const int m0 = blockIdx.y * 128;
    const int n0 = blockIdx.x * 128;

    // A (and B when transposed) load pattern: row = tid/2, 4-float chunk = (tid&1)*4
    const int ar = tid >> 1;
    const int ac = (tid & 1) * 4;
    // B load pattern (NN): row = tid/32 (0..7), col chunk = (tid&31)*4
    const int br = tid >> 5;
    const int bc = (tid & 31) * 4;

    const int ty = tid >> 4;   // 0..15
    const int tx = tid & 15;   // 0..15

    float acc[8][8];
#pragma unroll
    for (int i = 0; i < 8; i++)
#pragma unroll
        for (int j = 0; j < 8; j++) acc[i][j] = 0.f;

    for (int k0 = 0; k0 < K; k0 += 8) {
        float4 a4 = *(const float4*)(A + (long)(m0 + ar) * lda + (k0 + ac));
        float4 b4;
        if (TRANS_B) {
            b4 = *(const float4*)(B + (long)(n0 + ar) * ldb + (k0 + ac));
        } else {
            b4 = *(const float4*)(B + (long)(k0 + br) * ldb + (n0 + bc));
        }

        __syncthreads();  // previous tile fully consumed
        As[ac + 0][ar] = a4.x;
        As[ac + 1][ar] = a4.y;
        As[ac + 2][ar] = a4.z;
        As[ac + 3][ar] = a4.w;
        if (TRANS_B) {
            Bs[ac + 0][ar] = b4.x;
            Bs[ac + 1][ar] = b4.y;
            Bs[ac + 2][ar] = b4.z;
            Bs[ac + 3][ar] = b4.w;
        } else {
            *(float4*)&Bs[br][bc] = b4;
        }
        __syncthreads();

#pragma unroll
        for (int kk = 0; kk < 8; kk++) {
            float a[8], b[8];
            *(float4*)&a[0] = *(const float4*)&As[kk][ty * 8];
            *(float4*)&a[4] = *(const float4*)&As[kk][ty * 8 + 4];
            *(float4*)&b[0] = *(const float4*)&Bs[kk][tx * 8];
            *(float4*)&b[4] = *(const float4*)&Bs[kk][tx * 8 + 4];
#pragma unroll
            for (int i = 0; i < 8; i++)
#pragma unroll
                for (int j = 0; j < 8; j++)
                    acc[i][j] += a[i] * b[j];
        }
    }

#pragma unroll
    for (int i = 0; i < 8; i++) {
        float4 v0 = make_float4(acc[i][0], acc[i][1], acc[i][2], acc[i][3]);
        float4 v1 = make_float4(acc[i][4], acc[i][5], acc[i][6], acc[i][7]);
        float* cp = C + (long)(m0 + ty * 8 + i) * ldc + n0 + tx * 8;
        *(float4*)cp = v0;
        *(float4*)(cp + 4) = v1;
    }
}

// ---------------- RoPE + QKV split ----------------
// half-truncate rope: d in [0,32): freq = 2^(-10*d/31); d in [32,64): freq = 0 (identity)
// rotate: out[d] = x1*cos + x2*sin ; out[d+64] = -x1*sin + x2*cos
__global__ __launch_bounds__(256)
void rope_split_kernel()
{
    const int l = blockIdx.x;
    const float* pr = g_proj + (long)l * QKVDIM;

    // 20 rotated heads (16 Q + 4 K), 64 pairs each
    for (int p = threadIdx.x; p < 20 * 64; p += blockDim.x) {
        const int head = p >> 6;
        const int d = p & 63;
        float c, s;
        if (d < 32) {
            const float f = exp2f(-10.0f * (float)d * (1.0f / 31.0f));
            const float th = (float)l * f;
            sincosf(th, &s, &c);
        } else {
            c = 1.f;
            s = 0.f;
        }
        if (head < HQ) {
            const float x1 = pr[head * HD + d];
            const float x2 = pr[head * HD + d + 64];
            float* q = g_Q + ((long)head * LSEQ + l) * HD;
            q[d] = x1 * c + x2 * s;
            q[d + 64] = -x1 * s + x2 * c;
        } else {
            const int kh = head - HQ;
            const float x1 = pr[HQ * HD + kh * HD + d];
            const float x2 = pr[HQ * HD + kh * HD + d + 64];
            float* kp = g_K + ((long)kh * LSEQ + l) * HD;
            kp[d] = x1 * c + x2 * s;
            kp[d + 64] = -x1 * s + x2 * c;
        }
    }
    // V copy (layout change): g_V[h][l][d] = proj[l][2560 + h*128 + d]
    for (int i = threadIdx.x; i < HKV * HD; i += blockDim.x) {
        const int h = i >> 7;
        const int d = i & 127;
        g_V[((long)h * LSEQ + l) * HD + d] = pr[(HQ + HKV) * HD + i];
    }
}

// ---------------- masked softmax with sink (in-place on g_S) ----------------
// FAITHFUL quirk: -inf is placed where (q >= k && q < k+1024), i.e. attention
// goes to strictly-future keys OR keys >= 1024 behind. Sink is in denominator only.
__global__ __launch_bounds__(256)
void softmax_kernel(const float* __restrict__ sink)
{
    const int q = blockIdx.x;
    const int h = blockIdx.y;  // flat q-head index 0..15
    float* row = g_S + ((size_t)h * LSEQ + q) * LSEQ;
    const float scale = 0.0883883476483184f;  // 1/sqrt(128)
    const float sv = sink[h];

    __shared__ float red[256];
    const int t = threadIdx.x;

    float lm = -3.0e38f;
    for (int k = t; k < LSEQ; k += 256) {
        const bool masked = (q >= k) && (q < k + 1024);
        if (!masked) lm = fmaxf(lm, row[k] * scale);
    }
    red[t] = lm;
    __syncthreads();
    for (int off = 128; off > 0; off >>= 1) {
        if (t < off) red[t] = fmaxf(red[t], red[t + off]);
        __syncthreads();
    }
    const float m = fmaxf(red[0], sv);
    __syncthreads();

    float ls = 0.f;
    for (int k = t; k < LSEQ; k += 256) {
        const bool masked = (q >= k) && (q < k + 1024);
        if (!masked) ls += expf(row[k] * scale - m);
    }
    red[t] = ls;
    __syncthreads();
    for (int off = 128; off > 0; off >>= 1) {
        if (t < off) red[t] += red[t + off];
        __syncthreads();
    }
    const float inv = 1.0f / (red[0] + expf(sv - m));
    __syncthreads();

    for (int k = t; k < LSEQ; k += 256) {
        const bool masked = (q >= k) && (q < k + 1024);
        row[k] = masked ? 0.f : expf(row[k] * scale - m) * inv;
    }
}

// ---------------- launch ----------------
extern "C" void kernel_launch(void* const* d_in, const int* in_sizes, int n_in,
                              void* d_out, int out_size)
{
    (void)in_sizes; (void)n_in; (void)out_size;
    const float* x    = (const float*)d_in[0];  // (1, 2048, 2048)
    const float* Wqkv = (const float*)d_in[1];  // (2048, 3072)
    const float* Wo   = (const float*)d_in[2];  // (2048, 2048)
    const float* s    = (const float*)d_in[3];  // (1, 16)
    float* out = (float*)d_out;                 // (1, 2048, 2048)

    float *proj, *Q, *K, *V, *S, *AO;
    cudaGetSymbolAddress((void**)&proj, g_proj);
    cudaGetSymbolAddress((void**)&Q, g_Q);
    cudaGetSymbolAddress((void**)&K, g_K);
    cudaGetSymbolAddress((void**)&V, g_V);
    cudaGetSymbolAddress((void**)&S, g_S);
    cudaGetSymbolAddress((void**)&AO, g_AO);

    // 1) proj = x @ Wqkv   (2048 x 3072 x 2048)
    gemm_kernel<0><<<dim3(QKVDIM / 128, LSEQ / 128, 1), 256>>>(
        x, Wqkv, proj, LSEQ, QKVDIM, DMODEL, DMODEL, QKVDIM, QKVDIM,
        0L, 0L, 1, 0L);

    // 2) RoPE + split into Q[16][L][128], K[4][L][128], V[4][L][128]
    rope_split_kernel<<<LSEQ, 256>>>();

    // 3) S[qh] = Q[qh] @ K[qh/4]^T   (16 x 2048 x 2048 x 128), NT
    gemm_kernel<1><<<dim3(LSEQ / 128, LSEQ / 128, HQ), 256>>>(
        Q, K, S, LSEQ, LSEQ, HD, HD, HD, LSEQ,
        (long)LSEQ * HD, (long)LSEQ * HD, 4, (long)LSEQ * LSEQ);

    // 4) masked softmax with sink (in place)
    softmax_kernel<<<dim3(LSEQ, HQ), 256>>>(s);

    // 5) AO[:, qh*128:(qh+1)*128] = W[qh] @ V[qh/4]   (16 x 2048 x 128 x 2048), NN
    gemm_kernel<0><<<dim3(1, LSEQ / 128, HQ), 256>>>(
        S, V, AO, LSEQ, HD, LSEQ, LSEQ, HD, DMODEL,
        (long)LSEQ * LSEQ, (long)LSEQ * HD, 4, (long)HD);

    // 6) out = AO @ Wo   (2048 x 2048 x 2048)
    gemm_kernel<0><<<dim3(DMODEL / 128, LSEQ / 128, 1), 256>>>(
        AO, Wo, out, LSEQ, DMODEL, DMODEL, DMODEL, DMODEL, DMODEL,
        0L, 0L, 1, 0L);
}

// round 7
// speedup vs baseline: 2.0395x; 2.0395x over previous
#include <cuda_runtime.h>
#include <cuda_bf16.h>
#include <cstdint>
#include <math.h>

#define LSEQ 2048
#define DMODEL 2048
#define QKVDIM 3072
#define HQ 16
#define HKV 4
#define HD 128

// ---------------- device scratch (no allocation allowed) ----------------
__device__ __align__(16) __nv_bfloat16 g_xhi[(size_t)LSEQ * DMODEL];
__device__ __align__(16) __nv_bfloat16 g_xlo[(size_t)LSEQ * DMODEL];
__device__ __align__(16) float g_proj[(size_t)LSEQ * QKVDIM];
__device__ __align__(16) __nv_bfloat16 g_Qhi[(size_t)HQ * LSEQ * HD];
__device__ __align__(16) __nv_bfloat16 g_Qlo[(size_t)HQ * LSEQ * HD];
__device__ __align__(16) __nv_bfloat16 g_Khi[(size_t)HKV * LSEQ * HD];
__device__ __align__(16) __nv_bfloat16 g_Klo[(size_t)HKV * LSEQ * HD];
__device__ __align__(16) __nv_bfloat16 g_VThi[(size_t)HKV * HD * LSEQ];
__device__ __align__(16) __nv_bfloat16 g_VTlo[(size_t)HKV * HD * LSEQ];
__device__ __align__(16) __nv_bfloat16 g_WqkvT_hi[(size_t)QKVDIM * DMODEL];
__device__ __align__(16) __nv_bfloat16 g_WqkvT_lo[(size_t)QKVDIM * DMODEL];
__device__ __align__(16) __nv_bfloat16 g_WoT_hi[(size_t)DMODEL * DMODEL];
__device__ __align__(16) __nv_bfloat16 g_WoT_lo[(size_t)DMODEL * DMODEL];
__device__ __align__(16) float g_S[(size_t)HQ * LSEQ * LSEQ];        // 268 MB
__device__ __align__(16) __nv_bfloat16 g_Shi[(size_t)HQ * LSEQ * LSEQ];
__device__ __align__(16) __nv_bfloat16 g_Slo[(size_t)HQ * LSEQ * LSEQ];
__device__ __align__(16) __nv_bfloat16 g_AOhi[(size_t)LSEQ * DMODEL];
__device__ __align__(16) __nv_bfloat16 g_AOlo[(size_t)LSEQ * DMODEL];

// ---------------- helpers ----------------
__device__ __forceinline__ uint32_t smem_u32(const void* p) {
    uint32_t a;
    asm("{ .reg .u64 t; cvta.to.shared.u64 t, %1; cvt.u32.u64 %0, t; }" : "=r"(a) : "l"(p));
    return a;
}
__device__ __forceinline__ void cp16(uint32_t dst, const void* src) {
    asm volatile("cp.async.cg.shared.global [%0], [%1], 16;" :: "r"(dst), "l"(src) : "memory");
}
#define CP_COMMIT() asm volatile("cp.async.commit_group;" ::: "memory")
#define CP_WAIT0()  asm volatile("cp.async.wait_group 0;" ::: "memory")
__device__ __forceinline__ uint32_t lds32(uint32_t a) {
    uint32_t v;
    asm volatile("ld.shared.b32 %0, [%1];" : "=r"(v) : "r"(a));
    return v;
}
__device__ __forceinline__ void mma16816(float* c, const uint32_t* a, const uint32_t* b) {
    asm volatile(
        "mma.sync.aligned.m16n8k16.row.col.f32.bf16.bf16.f32 "
        "{%0,%1,%2,%3}, {%4,%5,%6,%7}, {%8,%9}, {%0,%1,%2,%3};"
        : "+f"(c[0]), "+f"(c[1]), "+f"(c[2]), "+f"(c[3])
        : "r"(a[0]), "r"(a[1]), "r"(a[2]), "r"(a[3]), "r"(b[0]), "r"(b[1]));
}

// ---------------- HMMA GEMM ----------------
// C[M,N] = Ahi/lo[M,K] * (Bhi/lo[N,K])^T  with 3-pass bf16 split (fp32 accuracy).
// Block tile 128x128, BK=32, 256 threads (8 warps, warp tile 64x32).
// smem per array per buffer: 128 rows * 80 bytes = 10240 B. 4 arrays x 2 bufs = 80 KB.
#define RB 80           // padded smem row stride in bytes (40 bf16) — conflict-free
#define BUFB 10240
#define OFF_AHI 0
#define OFF_ALO 20480
#define OFF_BHI 40960
#define OFF_BLO 61440
#define GSMEM 81920

__device__ __forceinline__ void issue_tiles(
    uint32_t sb, int buf,
    const __nv_bfloat16* Ahi, const __nv_bfloat16* Alo,
    const __nv_bfloat16* Bhi, const __nv_bfloat16* Blo,
    int m0, int n0, int k0, int lda, int ldb, int tid)
{
#pragma unroll
    for (int i = 0; i < 2; i++) {
        const int o = tid * 2 + i;
        const int r = o >> 2;
        const int ce = (o & 3) * 8;              // bf16 element col
        const uint32_t db = buf * BUFB + (unsigned)r * RB + (o & 3) * 16;
        const long ga = (long)(m0 + r) * lda + k0 + ce;
        const long gb = (long)(n0 + r) * ldb + k0 + ce;
        cp16(sb + OFF_AHI + db, Ahi + ga);
        cp16(sb + OFF_ALO + db, Alo + ga);
        cp16(sb + OFF_BHI + db, Bhi + gb);
        cp16(sb + OFF_BLO + db, Blo + gb);
    }
}

// EPI=0: write fp32 C.  EPI=1: write bf16 hi/lo pair (Chi/Clo).
template <int EPI>
__global__ __launch_bounds__(256)
void gemm_mma(const __nv_bfloat16* __restrict__ Ahi, const __nv_bfloat16* __restrict__ Alo,
              const __nv_bfloat16* __restrict__ Bhi, const __nv_bfloat16* __restrict__ Blo,
              float* __restrict__ C, __nv_bfloat16* __restrict__ Chi, __nv_bfloat16* __restrict__ Clo,
              int K, int lda, int ldb, int ldc,
              long aStr, long bStr, int bDiv, long cStr)
{
    extern __shared__ char smem[];
    const uint32_t sb = smem_u32(smem);
    const int tid = threadIdx.x;
    const int warp = tid >> 5;
    const int lane = tid & 31;
    const int wm = warp & 1;          // 2 warp rows (64 each)
    const int wn = warp >> 1;         // 4 warp cols (32 each)
    const int gid = lane >> 2;        // 0..7
    const int tg = lane & 3;          // 0..3
    const int z = blockIdx.z;

    Ahi += (long)z * aStr; Alo += (long)z * aStr;
    Bhi += (long)(z / bDiv) * bStr; Blo += (long)(z / bDiv) * bStr;

    const int m0 = blockIdx.y * 128;
    const int n0 = blockIdx.x * 128;

    float acc[4][4][4];
#pragma unroll
    for (int i = 0; i < 4; i++)
#pragma unroll
        for (int j = 0; j < 4; j++)
#pragma unroll
            for (int v = 0; v < 4; v++) acc[i][j][v] = 0.f;

    const int nch = K >> 5;
    issue_tiles(sb, 0, Ahi, Alo, Bhi, Blo, m0, n0, 0, lda, ldb, tid);
    CP_COMMIT();

    for (int ch = 0; ch < nch; ch++) {
        const int buf = ch & 1;
        CP_WAIT0();
        __syncthreads();
        if (ch + 1 < nch) {
            issue_tiles(sb, buf ^ 1, Ahi, Alo, Bhi, Blo, m0, n0, (ch + 1) << 5, lda, ldb, tid);
            CP_COMMIT();
        }

        const uint32_t abase = sb + buf * BUFB + (unsigned)(wm * 64 + gid) * RB;
        const uint32_t bbase = sb + buf * BUFB + (unsigned)(wn * 32 + gid) * RB;
#pragma unroll
        for (int ks = 0; ks < 2; ks++) {
            const uint32_t cb = (unsigned)(ks * 16 + tg * 2) * 2;  // byte col
            uint32_t ahi[4][4], alo[4][4], bhi[4][2], blo[4][2];
#pragma unroll
            for (int mf = 0; mf < 4; mf++) {
                const uint32_t a0 = abase + (unsigned)(mf * 16) * RB + cb;
                ahi[mf][0] = lds32(OFF_AHI + a0);
                ahi[mf][1] = lds32(OFF_AHI + a0 + 8 * RB);
                ahi[mf][2] = lds32(OFF_AHI + a0 + 16);
                ahi[mf][3] = lds32(OFF_AHI + a0 + 8 * RB + 16);
                alo[mf][0] = lds32(OFF_ALO + a0);
                alo[mf][1] = lds32(OFF_ALO + a0 + 8 * RB);
                alo[mf][2] = lds32(OFF_ALO + a0 + 16);
                alo[mf][3] = lds32(OFF_ALO + a0 + 8 * RB + 16);
            }
#pragma unroll
            for (int nf = 0; nf < 4; nf++) {
                const uint32_t b0 = bbase + (unsigned)(nf * 8) * RB + cb;
                bhi[nf][0] = lds32(OFF_BHI + b0);
                bhi[nf][1] = lds32(OFF_BHI + b0 + 16);
                blo[nf][0] = lds32(OFF_BLO + b0);
                blo[nf][1] = lds32(OFF_BLO + b0 + 16);
            }
#pragma unroll
            for (int mf = 0; mf < 4; mf++)
#pragma unroll
                for (int nf = 0; nf < 4; nf++) {
                    mma16816(acc[mf][nf], ahi[mf], bhi[nf]);
                    mma16816(acc[mf][nf], ahi[mf], blo[nf]);
                    mma16816(acc[mf][nf], alo[mf], bhi[nf]);
                }
        }
        __syncthreads();
    }

    // ---- epilogue ----
#pragma unroll
    for (int mf = 0; mf < 4; mf++) {
#pragma unroll
        for (int nf = 0; nf < 4; nf++) {
            const int r = m0 + wm * 64 + mf * 16 + gid;
            const int cc = n0 + wn * 32 + nf * 8 + tg * 2;
#pragma unroll
            for (int half = 0; half < 2; half++) {
                const long off = ((long)(r + half * 8) + (long)z * 0) * ldc + cc;
                const float v0 = acc[mf][nf][half * 2 + 0];
                const float v1 = acc[mf][nf][half * 2 + 1];
                if (EPI == 0) {
                    float2 o; o.x = v0; o.y = v1;
                    *(float2*)(C + (long)z * cStr + off) = o;
                } else {
                    const __nv_bfloat16 h0 = __float2bfloat16(v0);
                    const __nv_bfloat16 h1 = __float2bfloat16(v1);
                    __nv_bfloat162 hp, lp;
                    hp.x = h0; hp.y = h1;
                    lp.x = __float2bfloat16(v0 - __bfloat162float(h0));
                    lp.y = __float2bfloat16(v1 - __bfloat162float(h1));
                    *(__nv_bfloat162*)(Chi + (long)z * cStr + off) = hp;
                    *(__nv_bfloat162*)(Clo + (long)z * cStr + off) = lp;
                }
            }
        }
    }
}

// ---------------- fp32 -> bf16 hi/lo split (elementwise, vectorized) ----------------
__global__ __launch_bounds__(256)
void split_kernel(const float* __restrict__ in, __nv_bfloat16* __restrict__ oh,
                  __nv_bfloat16* __restrict__ ol, int n4)
{
    const int i = blockIdx.x * 256 + threadIdx.x;
    if (i >= n4) return;
    const float4 v = ((const float4*)in)[i];
    const float* e = (const float*)&v;
    __nv_bfloat16 h[4], l[4];
#pragma unroll
    for (int j = 0; j < 4; j++) {
        h[j] = __float2bfloat16(e[j]);
        l[j] = __float2bfloat16(e[j] - __bfloat162float(h[j]));
    }
    ((uint2*)oh)[i] = *(uint2*)h;
    ((uint2*)ol)[i] = *(uint2*)l;
}

// ---------------- transpose + split ----------------
__global__ __launch_bounds__(256)
void transpose_convert(const float* __restrict__ in,
                       __nv_bfloat16* __restrict__ oh, __nv_bfloat16* __restrict__ ol,
                       int ldi, int ldo, long inStr, long outStr)
{
    const int z = blockIdx.z;
    in += (long)z * inStr;
    oh += (long)z * outStr;
    ol += (long)z * outStr;
    __shared__ float tb[32][33];
    const int n0 = blockIdx.x * 32, k0 = blockIdx.y * 32;
    const int tx = threadIdx.x & 31, ty = threadIdx.x >> 5;
#pragma unroll
    for (int i = 0; i < 4; i++)
        tb[ty + i * 8][tx] = in[(long)(k0 + ty + i * 8) * ldi + n0 + tx];
    __syncthreads();
#pragma unroll
    for (int i = 0; i < 4; i++) {
        const int n = ty + i * 8;
        const float v = tb[tx][n];
        const __nv_bfloat16 h = __float2bfloat16(v);
        const long o = (long)(n0 + n) * ldo + k0 + tx;
        oh[o] = h;
        ol[o] = __float2bfloat16(v - __bfloat162float(h));
    }
}

// ---------------- RoPE + split: Q and K to bf16 hi/lo ----------------
__global__ __launch_bounds__(256)
void rope_split_kernel()
{
    const int l = blockIdx.x;
    const float* pr = g_proj + (long)l * QKVDIM;

    for (int p = threadIdx.x; p < 20 * 64; p += blockDim.x) {
        const int head = p >> 6;
        const int d = p & 63;
        float c, s;
        if (d < 32) {
            const float f = exp2f(-10.0f * (float)d * (1.0f / 31.0f));
            sincosf((float)l * f, &s, &c);
        } else { c = 1.f; s = 0.f; }
        float x1, x2;
        __nv_bfloat16 *dh, *dl;
        long base;
        if (head < HQ) {
            x1 = pr[head * HD + d];
            x2 = pr[head * HD + d + 64];
            base = ((long)head * LSEQ + l) * HD;
            dh = g_Qhi; dl = g_Qlo;
        } else {
            const int kh = head - HQ;
            x1 = pr[HQ * HD + kh * HD + d];
            x2 = pr[HQ * HD + kh * HD + d + 64];
            base = ((long)kh * LSEQ + l) * HD;
            dh = g_Khi; dl = g_Klo;
        }
        const float r0 = x1 * c + x2 * s;
        const float r1 = -x1 * s + x2 * c;
        const __nv_bfloat16 h0 = __float2bfloat16(r0);
        const __nv_bfloat16 h1 = __float2bfloat16(r1);
        dh[base + d] = h0;
        dh[base + d + 64] = h1;
        dl[base + d] = __float2bfloat16(r0 - __bfloat162float(h0));
        dl[base + d + 64] = __float2bfloat16(r1 - __bfloat162float(h1));
    }
}

// ---------------- masked softmax with sink -> bf16 hi/lo ----------------
// FAITHFUL quirk: -inf where (q >= k && q < k+1024). Sink in denominator only.
__global__ __launch_bounds__(256)
void softmax_kernel(const float* __restrict__ sink)
{
    const int q = blockIdx.x;
    const int h = blockIdx.y;
    const size_t base = ((size_t)h * LSEQ + q) * LSEQ;
    const float* row = g_S + base;
    const float scale = 0.0883883476483184f;  // 1/sqrt(128)
    const float sv = sink[h];
    const int t = threadIdx.x;
    __shared__ float sred[8];

    float4 v[2];
    float lm = -3.0e38f;
#pragma unroll
    for (int i = 0; i < 2; i++) {
        const int k4 = t + i * 256;
        v[i] = *(const float4*)(row + k4 * 4);
        float* e = (float*)&v[i];
#pragma unroll
        for (int j = 0; j < 4; j++) {
            const int k = k4 * 4 + j;
            const bool masked = (q >= k) && (q < k + 1024);
            e[j] = masked ? -1e30f : e[j] * scale;
            lm = fmaxf(lm, e[j]);
        }
    }
    float wr = lm;
#pragma unroll
    for (int o = 16; o; o >>= 1) wr = fmaxf(wr, __shfl_xor_sync(0xffffffffu, wr, o));
    if ((t & 31) == 0) sred[t >> 5] = wr;
    __syncthreads();
    float gm = sred[0];
#pragma unroll
    for (int w = 1; w < 8; w++) gm = fmaxf(gm, sred[w]);
    const float m = fmaxf(gm, sv);
    __syncthreads();

    float ls = 0.f;
#pragma unroll
    for (int i = 0; i < 2; i++) {
        float* e = (float*)&v[i];
#pragma unroll
        for (int j = 0; j < 4; j++) {
            e[j] = expf(e[j] - m);
            ls += e[j];
        }
    }
    float ws = ls;
#pragma unroll
    for (int o = 16; o; o >>= 1) ws += __shfl_xor_sync(0xffffffffu, ws, o);
    if ((t & 31) == 0) sred[t >> 5] = ws;
    __syncthreads();
    float gs = 0.f;
#pragma unroll
    for (int w = 0; w < 8; w++) gs += sred[w];
    const float inv = 1.0f / (gs + expf(sv - m));

#pragma unroll
    for (int i = 0; i < 2; i++) {
        const int k4 = t + i * 256;
        float* e = (float*)&v[i];
        __nv_bfloat16 hh[4], ll[4];
#pragma unroll
        for (int j = 0; j < 4; j++) {
            const float w = e[j] * inv;
            hh[j] = __float2bfloat16(w);
            ll[j] = __float2bfloat16(w - __bfloat162float(hh[j]));
        }
        *(uint2*)(g_Shi + base + k4 * 4) = *(uint2*)hh;
        *(uint2*)(g_Slo + base + k4 * 4) = *(uint2*)ll;
    }
}

// ---------------- launch ----------------
extern "C" void kernel_launch(void* const* d_in, const int* in_sizes, int n_in,
                              void* d_out, int out_size)
{
    (void)in_sizes; (void)n_in; (void)out_size;
    const float* x    = (const float*)d_in[0];
    const float* Wqkv = (const float*)d_in[1];
    const float* Wo   = (const float*)d_in[2];
    const float* s    = (const float*)d_in[3];
    float* out = (float*)d_out;

    cudaFuncSetAttribute(gemm_mma<0>, cudaFuncAttributeMaxDynamicSharedMemorySize, GSMEM);
    cudaFuncSetAttribute(gemm_mma<1>, cudaFuncAttributeMaxDynamicSharedMemorySize, GSMEM);

    float *proj, *S;
    __nv_bfloat16 *xhi, *xlo, *Qhi, *Qlo, *Khi, *Klo, *VThi, *VTlo;
    __nv_bfloat16 *WqT_h, *WqT_l, *WoT_h, *WoT_l, *Shi, *Slo, *AOhi, *AOlo;
    cudaGetSymbolAddress((void**)&proj, g_proj);
    cudaGetSymbolAddress((void**)&S, g_S);
    cudaGetSymbolAddress((void**)&xhi, g_xhi);
    cudaGetSymbolAddress((void**)&xlo, g_xlo);
    cudaGetSymbolAddress((void**)&Qhi, g_Qhi);
    cudaGetSymbolAddress((void**)&Qlo, g_Qlo);
    cudaGetSymbolAddress((void**)&Khi, g_Khi);
    cudaGetSymbolAddress((void**)&Klo, g_Klo);
    cudaGetSymbolAddress((void**)&VThi, g_VThi);
    cudaGetSymbolAddress((void**)&VTlo, g_VTlo);
    cudaGetSymbolAddress((void**)&WqT_h, g_WqkvT_hi);
    cudaGetSymbolAddress((void**)&WqT_l, g_WqkvT_lo);
    cudaGetSymbolAddress((void**)&WoT_h, g_WoT_hi);
    cudaGetSymbolAddress((void**)&WoT_l, g_WoT_lo);
    cudaGetSymbolAddress((void**)&Shi, g_Shi);
    cudaGetSymbolAddress((void**)&Slo, g_Slo);
    cudaGetSymbolAddress((void**)&AOhi, g_AOhi);
    cudaGetSymbolAddress((void**)&AOlo, g_AOlo);

    // 0) operand prep
    split_kernel<<<(LSEQ * DMODEL / 4 + 255) / 256, 256>>>(x, xhi, xlo, LSEQ * DMODEL / 4);
    transpose_convert<<<dim3(QKVDIM / 32, DMODEL / 32, 1), 256>>>(
        Wqkv, WqT_h, WqT_l, QKVDIM, DMODEL, 0L, 0L);
    transpose_convert<<<dim3(DMODEL / 32, DMODEL / 32, 1), 256>>>(
        Wo, WoT_h, WoT_l, DMODEL, DMODEL, 0L, 0L);

    // 1) proj = x @ Wqkv  (M=2048, N=3072, K=2048)
    gemm_mma<0><<<dim3(QKVDIM / 128, LSEQ / 128, 1), 256, GSMEM>>>(
        xhi, xlo, WqT_h, WqT_l, proj, nullptr, nullptr,
        DMODEL, DMODEL, DMODEL, QKVDIM, 0L, 0L, 1, 0L);

    // 2) RoPE -> Q/K hi/lo ; V transpose -> VT hi/lo
    rope_split_kernel<<<LSEQ, 256>>>();
    transpose_convert<<<dim3(HD / 32, LSEQ / 32, HKV), 256>>>(
        proj + (HQ + HKV) * HD, VThi, VTlo, QKVDIM, LSEQ, (long)HD, (long)HD * LSEQ);

    // 3) S[h] = Q[h] @ K[h/4]^T  (M=2048, N=2048, K=128) x16
    gemm_mma<0><<<dim3(LSEQ / 128, LSEQ / 128, HQ), 256, GSMEM>>>(
        Qhi, Qlo, Khi, Klo, S, nullptr, nullptr,
        HD, HD, HD, LSEQ, (long)LSEQ * HD, (long)LSEQ * HD, 4, (long)LSEQ * LSEQ);

    // 4) masked softmax + sink -> S hi/lo
    softmax_kernel<<<dim3(LSEQ, HQ), 256>>>(s);

    // 5) AO[:, h*128:] = W[h] @ V[h/4]  (M=2048, N=128, K=2048) x16, split epilogue
    gemm_mma<1><<<dim3(1, LSEQ / 128, HQ), 256, GSMEM>>>(
        Shi, Slo, VThi, VTlo, nullptr, AOhi, AOlo,
        LSEQ, LSEQ, LSEQ, DMODEL, (long)LSEQ * LSEQ, (long)HD * LSEQ, 4, (long)HD);

    // 6) out = AO @ Wo  (M=2048, N=2048, K=2048)
    gemm_mma<0><<<dim3(DMODEL / 128, LSEQ / 128, 1), 256, GSMEM>>>(
        AOhi, AOlo, WoT_h, WoT_l, out, nullptr, nullptr,
        DMODEL, DMODEL, DMODEL, DMODEL, 0L, 0L, 1, 0L);
}

// round 9
// speedup vs baseline: 2.3989x; 1.1762x over previous
#include <cuda_runtime.h>
#include <cuda_bf16.h>
#include <cstdint>
#include <math.h>

#define LSEQ 2048
#define DMODEL 2048
#define QKVDIM 3072
#define HQ 16
#define HKV 4
#define HD 128

// ---------------- device scratch (no allocation allowed) ----------------
__device__ __align__(16) __nv_bfloat16 g_xhi[(size_t)LSEQ * DMODEL];
__device__ __align__(16) __nv_bfloat16 g_xlo[(size_t)LSEQ * DMODEL];
__device__ __align__(16) float g_proj[(size_t)LSEQ * QKVDIM];
__device__ __align__(16) __nv_bfloat16 g_Qhi[(size_t)HQ * LSEQ * HD];
__device__ __align__(16) __nv_bfloat16 g_Qlo[(size_t)HQ * LSEQ * HD];
__device__ __align__(16) __nv_bfloat16 g_Khi[(size_t)HKV * LSEQ * HD];
__device__ __align__(16) __nv_bfloat16 g_Klo[(size_t)HKV * LSEQ * HD];
__device__ __align__(16) __nv_bfloat16 g_VThi[(size_t)HKV * HD * LSEQ];
__device__ __align__(16) __nv_bfloat16 g_VTlo[(size_t)HKV * HD * LSEQ];
__device__ __align__(16) __nv_bfloat16 g_WqkvT_hi[(size_t)QKVDIM * DMODEL];
__device__ __align__(16) __nv_bfloat16 g_WqkvT_lo[(size_t)QKVDIM * DMODEL];
__device__ __align__(16) __nv_bfloat16 g_WoT_hi[(size_t)DMODEL * DMODEL];
__device__ __align__(16) __nv_bfloat16 g_WoT_lo[(size_t)DMODEL * DMODEL];
__device__ __align__(16) float g_S[(size_t)HQ * LSEQ * LSEQ];        // 268 MB
__device__ __align__(16) __nv_bfloat16 g_Shi[(size_t)HQ * LSEQ * LSEQ];
__device__ __align__(16) __nv_bfloat16 g_Slo[(size_t)HQ * LSEQ * LSEQ];
__device__ __align__(16) __nv_bfloat16 g_AOhi[(size_t)LSEQ * DMODEL];
__device__ __align__(16) __nv_bfloat16 g_AOlo[(size_t)LSEQ * DMODEL];

// ---------------- helpers ----------------
__device__ __forceinline__ uint32_t smem_u32(const void* p) {
    uint32_t a;
    asm("{ .reg .u64 t; cvta.to.shared.u64 t, %1; cvt.u32.u64 %0, t; }" : "=r"(a) : "l"(p));
    return a;
}
__device__ __forceinline__ void cp16(uint32_t dst, const void* src) {
    asm volatile("cp.async.cg.shared.global [%0], [%1], 16;" :: "r"(dst), "l"(src) : "memory");
}
#define CP_COMMIT() asm volatile("cp.async.commit_group;" ::: "memory")
#define CP_WAIT0()  asm volatile("cp.async.wait_group 0;" ::: "memory")
__device__ __forceinline__ void ldm_x4(uint32_t* r, uint32_t addr) {
    asm volatile("ldmatrix.sync.aligned.m8n8.x4.shared.b16 {%0,%1,%2,%3}, [%4];"
        : "=r"(r[0]), "=r"(r[1]), "=r"(r[2]), "=r"(r[3]) : "r"(addr));
}
__device__ __forceinline__ void mma16816(float* c, const uint32_t* a, const uint32_t* b) {
    asm volatile(
        "mma.sync.aligned.m16n8k16.row.col.f32.bf16.bf16.f32 "
        "{%0,%1,%2,%3}, {%4,%5,%6,%7}, {%8,%9}, {%0,%1,%2,%3};"
        : "+f"(c[0]), "+f"(c[1]), "+f"(c[2]), "+f"(c[3])
        : "r"(a[0]), "r"(a[1]), "r"(a[2]), "r"(a[3]), "r"(b[0]), "r"(b[1]));
}

// ---------------- HMMA GEMM ----------------
// C[M,N] = Ahi/lo[M,K] * (Bhi/lo[N,K])^T  with 3-pass bf16 split (fp32 accuracy).
// Block tile 128x128, BK=32, 256 threads (8 warps, warp tile 64x32), 2 CTAs/SM.
// smem per array per buffer: 128 rows * 80 bytes = 10240 B. 4 arrays x 2 bufs = 80 KB.
#define RB 80           // padded smem row stride in bytes (40 bf16) — conflict-free
#define BUFB 10240
#define OFF_AHI 0
#define OFF_ALO 20480
#define OFF_BHI 40960
#define OFF_BLO 61440
#define GSMEM 81920

__device__ __forceinline__ void issue_tiles(
    uint32_t sb, int buf,
    const __nv_bfloat16* Ahi, const __nv_bfloat16* Alo,
    const __nv_bfloat16* Bhi, const __nv_bfloat16* Blo,
    int m0, int n0, int k0, int lda, int ldb, int tid)
{
#pragma unroll
    for (int i = 0; i < 2; i++) {
        const int o = tid * 2 + i;
        const int r = o >> 2;
        const int ce = (o & 3) * 8;              // bf16 element col
        const uint32_t db = buf * BUFB + (unsigned)r * RB + (o & 3) * 16;
        const long ga = (long)(m0 + r) * lda + k0 + ce;
        const long gb = (long)(n0 + r) * ldb + k0 + ce;
        cp16(sb + OFF_AHI + db, Ahi + ga);
        cp16(sb + OFF_ALO + db, Alo + ga);
        cp16(sb + OFF_BHI + db, Bhi + gb);
        cp16(sb + OFF_BLO + db, Blo + gb);
    }
}

// EPI=0: write fp32 C.  EPI=1: write bf16 hi/lo pair (Chi/Clo).
template <int EPI>
__global__ __launch_bounds__(256, 2)
void gemm_mma(const __nv_bfloat16* __restrict__ Ahi, const __nv_bfloat16* __restrict__ Alo,
              const __nv_bfloat16* __restrict__ Bhi, const __nv_bfloat16* __restrict__ Blo,
              float* __restrict__ C, __nv_bfloat16* __restrict__ Chi, __nv_bfloat16* __restrict__ Clo,
              int K, int lda, int ldb, int ldc,
              long aStr, long bStr, int bDiv, long cStr)
{
    extern __shared__ char smem[];
    const uint32_t sb = smem_u32(smem);
    const int tid = threadIdx.x;
    const int warp = tid >> 5;
    const int lane = tid & 31;
    const int wm = warp & 1;          // 2 warp rows (64 each)
    const int wn = warp >> 1;         // 4 warp cols (32 each)
    const int gid = lane >> 2;        // 0..7
    const int tg = lane & 3;          // 0..3
    const int z = blockIdx.z;

    Ahi += (long)z * aStr; Alo += (long)z * aStr;
    Bhi += (long)(z / bDiv) * bStr; Blo += (long)(z / bDiv) * bStr;

    const int m0 = blockIdx.y * 128;
    const int n0 = blockIdx.x * 128;

    // ldmatrix lane address components (within buffer, before OFF_* / buf / mf / ks)
    // A x4: matrices (rows0-7,k0-15 lo8)(rows8-15,lo8)(rows0-7,hi8)(rows8-15,hi8)
    const uint32_t arow = (unsigned)(wm * 64 + (lane & 7) + ((lane >> 3) & 1) * 8);
    const uint32_t acol = (unsigned)((lane >> 4) * 16);
    const uint32_t aoff = arow * RB + acol;
    // B x4: matrices (nf_even,k0-7)(nf_even,k8-15)(nf_odd,k0-7)(nf_odd,k8-15)
    const uint32_t brow = (unsigned)(wn * 32 + ((lane >> 4) * 8) + (lane & 7));
    const uint32_t bcol = (unsigned)(((lane >> 3) & 1) * 16);
    const uint32_t boff = brow * RB + bcol;

    float acc[4][4][4];
#pragma unroll
    for (int i = 0; i < 4; i++)
#pragma unroll
        for (int j = 0; j < 4; j++)
#pragma unroll
            for (int v = 0; v < 4; v++) acc[i][j][v] = 0.f;

    const int nch = K >> 5;
    issue_tiles(sb, 0, Ahi, Alo, Bhi, Blo, m0, n0, 0, lda, ldb, tid);
    CP_COMMIT();

    for (int ch = 0; ch < nch; ch++) {
        const int buf = ch & 1;
        CP_WAIT0();
        __syncthreads();
        if (ch + 1 < nch) {
            issue_tiles(sb, buf ^ 1, Ahi, Alo, Bhi, Blo, m0, n0, (ch + 1) << 5, lda, ldb, tid);
            CP_COMMIT();
        }

        const uint32_t abase = sb + buf * BUFB + aoff;
        const uint32_t bbase = sb + buf * BUFB + boff;
#pragma unroll
        for (int ks = 0; ks < 2; ks++) {
            uint32_t ahi[4][4], alo[4][4];
#pragma unroll
            for (int mf = 0; mf < 4; mf++) {
                const uint32_t a0 = abase + (unsigned)(mf * 16) * RB + (unsigned)(ks * 32);
                ldm_x4(ahi[mf], OFF_AHI + a0);
                ldm_x4(alo[mf], OFF_ALO + a0);
            }
#pragma unroll
            for (int nfp = 0; nfp < 2; nfp++) {
                uint32_t bh[4], bl[4];
                const uint32_t b0 = bbase + (unsigned)(nfp * 16) * RB + (unsigned)(ks * 32);
                ldm_x4(bh, OFF_BHI + b0);
                ldm_x4(bl, OFF_BLO + b0);
#pragma unroll
                for (int mf = 0; mf < 4; mf++) {
                    mma16816(acc[mf][nfp * 2 + 0], ahi[mf], bh + 0);
                    mma16816(acc[mf][nfp * 2 + 0], ahi[mf], bl + 0);
                    mma16816(acc[mf][nfp * 2 + 0], alo[mf], bh + 0);
                    mma16816(acc[mf][nfp * 2 + 1], ahi[mf], bh + 2);
                    mma16816(acc[mf][nfp * 2 + 1], ahi[mf], bl + 2);
                    mma16816(acc[mf][nfp * 2 + 1], alo[mf], bh + 2);
                }
            }
        }
        __syncthreads();
    }

    // ---- epilogue ----
#pragma unroll
    for (int mf = 0; mf < 4; mf++) {
#pragma unroll
        for (int nf = 0; nf < 4; nf++) {
            const int r = m0 + wm * 64 + mf * 16 + gid;
            const int cc = n0 + wn * 32 + nf * 8 + tg * 2;
#pragma unroll
            for (int half = 0; half < 2; half++) {
                const long off = (long)(r + half * 8) * ldc + cc;
                const float v0 = acc[mf][nf][half * 2 + 0];
                const float v1 = acc[mf][nf][half * 2 + 1];
                if (EPI == 0) {
                    float2 o; o.x = v0; o.y = v1;
                    *(float2*)(C + (long)z * cStr + off) = o;
                } else {
                    const __nv_bfloat16 h0 = __float2bfloat16(v0);
                    const __nv_bfloat16 h1 = __float2bfloat16(v1);
                    __nv_bfloat162 hp, lp;
                    hp.x = h0; hp.y = h1;
                    lp.x = __float2bfloat16(v0 - __bfloat162float(h0));
                    lp.y = __float2bfloat16(v1 - __bfloat162float(h1));
                    *(__nv_bfloat162*)(Chi + (long)z * cStr + off) = hp;
                    *(__nv_bfloat162*)(Clo + (long)z * cStr + off) = lp;
                }
            }
        }
    }
}

// ---------------- fp32 -> bf16 hi/lo split (elementwise, vectorized) ----------------
__global__ __launch_bounds__(256)
void split_kernel(const float* __restrict__ in, __nv_bfloat16* __restrict__ oh,
                  __nv_bfloat16* __restrict__ ol, int n4)
{
    const int i = blockIdx.x * 256 + threadIdx.x;
    if (i >= n4) return;
    const float4 v = ((const float4*)in)[i];
    const float* e = (const float*)&v;
    __nv_bfloat16 h[4], l[4];
#pragma unroll
    for (int j = 0; j < 4; j++) {
        h[j] = __float2bfloat16(e[j]);
        l[j] = __float2bfloat16(e[j] - __bfloat162float(h[j]));
    }
    ((uint2*)oh)[i] = *(uint2*)h;
    ((uint2*)ol)[i] = *(uint2*)l;
}

// ---------------- transpose + split ----------------
__global__ __launch_bounds__(256)
void transpose_convert(const float* __restrict__ in,
                       __nv_bfloat16* __restrict__ oh, __nv_bfloat16* __restrict__ ol,
                       int ldi, int ldo, long inStr, long outStr)
{
    const int z = blockIdx.z;
    in += (long)z * inStr;
    oh += (long)z * outStr;
    ol += (long)z * outStr;
    __shared__ float tb[32][33];
    const int n0 = blockIdx.x * 32, k0 = blockIdx.y * 32;
    const int tx = threadIdx.x & 31, ty = threadIdx.x >> 5;
#pragma unroll
    for (int i = 0; i < 4; i++)
        tb[ty + i * 8][tx] = in[(long)(k0 + ty + i * 8) * ldi + n0 + tx];
    __syncthreads();
#pragma unroll
    for (int i = 0; i < 4; i++) {
        const int n = ty + i * 8;
        const float v = tb[tx][n];
        const __nv_bfloat16 h = __float2bfloat16(v);
        const long o = (long)(n0 + n) * ldo + k0 + tx;
        oh[o] = h;
        ol[o] = __float2bfloat16(v - __bfloat162float(h));
    }
}

// ---------------- RoPE + split: Q and K to bf16 hi/lo ----------------
__global__ __launch_bounds__(256)
void rope_split_kernel()
{
    const int l = blockIdx.x;
    const float* pr = g_proj + (long)l * QKVDIM;

    for (int p = threadIdx.x; p < 20 * 64; p += blockDim.x) {
        const int head = p >> 6;
        const int d = p & 63;
        float c, s;
        if (d < 32) {
            const float f = exp2f(-10.0f * (float)d * (1.0f / 31.0f));
            sincosf((float)l * f, &s, &c);
        } else { c = 1.f; s = 0.f; }
        float x1, x2;
        __nv_bfloat16 *dh, *dl;
        long base;
        if (head < HQ) {
            x1 = pr[head * HD + d];
            x2 = pr[head * HD + d + 64];
            base = ((long)head * LSEQ + l) * HD;
            dh = g_Qhi; dl = g_Qlo;
        } else {
            const int kh = head - HQ;
            x1 = pr[HQ * HD + kh * HD + d];
            x2 = pr[HQ * HD + kh * HD + d + 64];
            base = ((long)kh * LSEQ + l) * HD;
            dh = g_Khi; dl = g_Klo;
        }
        const float r0 = x1 * c + x2 * s;
        const float r1 = -x1 * s + x2 * c;
        const __nv_bfloat16 h0 = __float2bfloat16(r0);
        const __nv_bfloat16 h1 = __float2bfloat16(r1);
        dh[base + d] = h0;
        dh[base + d + 64] = h1;
        dl[base + d] = __float2bfloat16(r0 - __bfloat162float(h0));
        dl[base + d + 64] = __float2bfloat16(r1 - __bfloat162float(h1));
    }
}

// ---------------- masked softmax with sink -> bf16 hi/lo ----------------
// FAITHFUL quirk: -inf where (q >= k && q < k+1024). Sink in denominator only.
__global__ __launch_bounds__(256)
void softmax_kernel(const float* __restrict__ sink)
{
    const int q = blockIdx.x;
    const int h = blockIdx.y;
    const size_t base = ((size_t)h * LSEQ + q) * LSEQ;
    const float* row = g_S + base;
    const float scale = 0.0883883476483184f;  // 1/sqrt(128)
    const float sv = sink[h];
    const int t = threadIdx.x;
    __shared__ float sred[8];

    float4 v[2];
    float lm = -3.0e38f;
#pragma unroll
    for (int i = 0; i < 2; i++) {
        const int k4 = t + i * 256;
        v[i] = *(const float4*)(row + k4 * 4);
        float* e = (float*)&v[i];
#pragma unroll
        for (int j = 0; j < 4; j++) {
            const int k = k4 * 4 + j;
            const bool masked = (q >= k) && (q < k + 1024);
            e[j] = masked ? -1e30f : e[j] * scale;
            lm = fmaxf(lm, e[j]);
        }
    }
    float wr = lm;
#pragma unroll
    for (int o = 16; o; o >>= 1) wr = fmaxf(wr, __shfl_xor_sync(0xffffffffu, wr, o));
    if ((t & 31) == 0) sred[t >> 5] = wr;
    __syncthreads();
    float gm = sred[0];
#pragma unroll
    for (int w = 1; w < 8; w++) gm = fmaxf(gm, sred[w]);
    const float m = fmaxf(gm, sv);
    __syncthreads();

    float ls = 0.f;
#pragma unroll
    for (int i = 0; i < 2; i++) {
        float* e = (float*)&v[i];
#pragma unroll
        for (int j = 0; j < 4; j++) {
            e[j] = expf(e[j] - m);
            ls += e[j];
        }
    }
    float ws = ls;
#pragma unroll
    for (int o = 16; o; o >>= 1) ws += __shfl_xor_sync(0xffffffffu, ws, o);
    if ((t & 31) == 0) sred[t >> 5] = ws;
    __syncthreads();
    float gs = 0.f;
#pragma unroll
    for (int w = 0; w < 8; w++) gs += sred[w];
    const float inv = 1.0f / (gs + expf(sv - m));

#pragma unroll
    for (int i = 0; i < 2; i++) {
        const int k4 = t + i * 256;
        float* e = (float*)&v[i];
        __nv_bfloat16 hh[4], ll[4];
#pragma unroll
        for (int j = 0; j < 4; j++) {
            const float w = e[j] * inv;
            hh[j] = __float2bfloat16(w);
            ll[j] = __float2bfloat16(w - __bfloat162float(hh[j]));
        }
        *(uint2*)(g_Shi + base + k4 * 4) = *(uint2*)hh;
        *(uint2*)(g_Slo + base + k4 * 4) = *(uint2*)ll;
    }
}

// ---------------- launch ----------------
extern "C" void kernel_launch(void* const* d_in, const int* in_sizes, int n_in,
                              void* d_out, int out_size)
{
    (void)in_sizes; (void)n_in; (void)out_size;
    const float* x    = (const float*)d_in[0];
    const float* Wqkv = (const float*)d_in[1];
    const float* Wo   = (const float*)d_in[2];
    const float* s    = (const float*)d_in[3];
    float* out = (float*)d_out;

    cudaFuncSetAttribute(gemm_mma<0>, cudaFuncAttributeMaxDynamicSharedMemorySize, GSMEM);
    cudaFuncSetAttribute(gemm_mma<1>, cudaFuncAttributeMaxDynamicSharedMemorySize, GSMEM);

    float *proj, *S;
    __nv_bfloat16 *xhi, *xlo, *Qhi, *Qlo, *Khi, *Klo, *VThi, *VTlo;
    __nv_bfloat16 *WqT_h, *WqT_l, *WoT_h, *WoT_l, *Shi, *Slo, *AOhi, *AOlo;
    cudaGetSymbolAddress((void**)&proj, g_proj);
    cudaGetSymbolAddress((void**)&S, g_S);
    cudaGetSymbolAddress((void**)&xhi, g_xhi);
    cudaGetSymbolAddress((void**)&xlo, g_xlo);
    cudaGetSymbolAddress((void**)&Qhi, g_Qhi);
    cudaGetSymbolAddress((void**)&Qlo, g_Qlo);
    cudaGetSymbolAddress((void**)&Khi, g_Khi);
    cudaGetSymbolAddress((void**)&Klo, g_Klo);
    cudaGetSymbolAddress((void**)&VThi, g_VThi);
    cudaGetSymbolAddress((void**)&VTlo, g_VTlo);
    cudaGetSymbolAddress((void**)&WqT_h, g_WqkvT_hi);
    cudaGetSymbolAddress((void**)&WqT_l, g_WqkvT_lo);
    cudaGetSymbolAddress((void**)&WoT_h, g_WoT_hi);
    cudaGetSymbolAddress((void**)&WoT_l, g_WoT_lo);
    cudaGetSymbolAddress((void**)&Shi, g_Shi);
    cudaGetSymbolAddress((void**)&Slo, g_Slo);
    cudaGetSymbolAddress((void**)&AOhi, g_AOhi);
    cudaGetSymbolAddress((void**)&AOlo, g_AOlo);

    // 0) operand prep
    split_kernel<<<(LSEQ * DMODEL / 4 + 255) / 256, 256>>>(x, xhi, xlo, LSEQ * DMODEL / 4);
    transpose_convert<<<dim3(QKVDIM / 32, DMODEL / 32, 1), 256>>>(
        Wqkv, WqT_h, WqT_l, QKVDIM, DMODEL, 0L, 0L);
    transpose_convert<<<dim3(DMODEL / 32, DMODEL / 32, 1), 256>>>(
        Wo, WoT_h, WoT_l, DMODEL, DMODEL, 0L, 0L);

    // 1) proj = x @ Wqkv  (M=2048, N=3072, K=2048)
    gemm_mma<0><<<dim3(QKVDIM / 128, LSEQ / 128, 1), 256, GSMEM>>>(
        xhi, xlo, WqT_h, WqT_l, proj, nullptr, nullptr,
        DMODEL, DMODEL, DMODEL, QKVDIM, 0L, 0L, 1, 0L);

    // 2) RoPE -> Q/K hi/lo ; V transpose -> VT hi/lo
    rope_split_kernel<<<LSEQ, 256>>>();
    transpose_convert<<<dim3(HD / 32, LSEQ / 32, HKV), 256>>>(
        proj + (HQ + HKV) * HD, VThi, VTlo, QKVDIM, LSEQ, (long)HD, (long)HD * LSEQ);

    // 3) S[h] = Q[h] @ K[h/4]^T  (M=2048, N=2048, K=128) x16
    gemm_mma<0><<<dim3(LSEQ / 128, LSEQ / 128, HQ), 256, GSMEM>>>(
        Qhi, Qlo, Khi, Klo, S, nullptr, nullptr,
        HD, HD, HD, LSEQ, (long)LSEQ * HD, (long)LSEQ * HD, 4, (long)LSEQ * LSEQ);

    // 4) masked softmax + sink -> S hi/lo
    softmax_kernel<<<dim3(LSEQ, HQ), 256>>>(s);

    // 5) AO[:, h*128:] = W[h] @ V[h/4]  (M=2048, N=128, K=2048) x16, split epilogue
    gemm_mma<1><<<dim3(1, LSEQ / 128, HQ), 256, GSMEM>>>(
        Shi, Slo, VThi, VTlo, nullptr, AOhi, AOlo,
        LSEQ, LSEQ, LSEQ, DMODEL, (long)LSEQ * LSEQ, (long)HD * LSEQ, 4, (long)HD);

    // 6) out = AO @ Wo  (M=2048, N=2048, K=2048)
    gemm_mma<0><<<dim3(DMODEL / 128, LSEQ / 128, 1), 256, GSMEM>>>(
        AOhi, AOlo, WoT_h, WoT_l, out, nullptr, nullptr,
        DMODEL, DMODEL, DMODEL, DMODEL, 0L, 0L, 1, 0L);
}